// round 1
// baseline (speedup 1.0000x reference)
#include <cuda_runtime.h>
#include <cuda_bf16.h>

// Problem: word_vecs [B=2048, S=200, D=300] fp32 -> masked mean over S -> [B, D].
// A masked (all-zero) word contributes 0 to the sum, so the sum needs no mask;
// only the count does.

#define B_DIM 2048
#define S_DIM 200
#define D_DIM 300
#define VDIM  75   // 300 floats = 75 float4 per word (1200 B, 16B-aligned stride)
#define NTHREADS 96

__global__ __launch_bounds__(NTHREADS)
void sentence_rep_kernel(const float4* __restrict__ in, float4* __restrict__ out) {
    __shared__ unsigned char flags[S_DIM];
    __shared__ float inv_count;

    const int b = blockIdx.x;
    const int t = threadIdx.x;
    const bool active = (t < VDIM);

    // zero the per-word flags
    for (int i = t; i < S_DIM; i += NTHREADS) flags[i] = 0;
    __syncthreads();

    const float4* __restrict__ row = in + (size_t)b * (S_DIM * VDIM);

    float4 acc = make_float4(0.f, 0.f, 0.f, 0.f);

    #pragma unroll 4
    for (int s = 0; s < S_DIM; ++s) {
        float4 v = make_float4(0.f, 0.f, 0.f, 0.f);
        if (active) v = row[s * VDIM + t];
        acc.x += v.x; acc.y += v.y; acc.z += v.z; acc.w += v.w;

        // per-word any-nonzero predicate (benign-race write of the same value)
        bool nz = (v.x != 0.f) || (v.y != 0.f) || (v.z != 0.f) || (v.w != 0.f);
        unsigned m = __ballot_sync(0xffffffffu, nz);
        if (((t & 31) == 0) && m) flags[s] = 1;
    }
    __syncthreads();

    // warp 0 reduces the 200 flags -> count -> 1/count
    if (t < 32) {
        int c = 0;
        for (int i = t; i < S_DIM; i += 32) c += (int)flags[i];
        #pragma unroll
        for (int o = 16; o > 0; o >>= 1) c += __shfl_down_sync(0xffffffffu, c, o);
        if (t == 0) inv_count = 1.0f / (float)c;   // count >= 1 guaranteed
    }
    __syncthreads();

    if (active) {
        const float ic = inv_count;
        out[(size_t)b * VDIM + t] =
            make_float4(acc.x * ic, acc.y * ic, acc.z * ic, acc.w * ic);
    }
}

extern "C" void kernel_launch(void* const* d_in, const int* in_sizes, int n_in,
                              void* d_out, int out_size) {
    (void)in_sizes; (void)n_in; (void)out_size;
    const float4* in = (const float4*)d_in[0];
    float4* out = (float4*)d_out;
    sentence_rep_kernel<<<B_DIM, NTHREADS>>>(in, out);
}